// round 1
// baseline (speedup 1.0000x reference)
#include <cuda_runtime.h>

#define BS 8
#define LQ 2049
#define NC 32
#define NH 16
#define KS 5
#define NL 4
#define NPOS (BS*LQ)            // 16392
#define NTILE 513               // ceil(NPOS/32)
#define KA 584                  // 512 Gsum + 32 fsum + 32 enc + 1 one + 7 pad
#define TILE_ELEMS (KA*NC)      // 18688

// -------- device scratch (globals: allowed; no allocation) --------
__device__ __align__(16) float g_times[BS*LQ];
__device__ __align__(16) float g_enc[NPOS*NC];
__device__ __align__(16) float g_raw[NTILE*32*NC];
__device__ __align__(16) float g_A[NTILE*TILE_ELEMS];      // ~38 MB
__device__ __align__(16) float g_Wc[NL*TILE_ELEMS];
__device__ __align__(16) float g_psum[NTILE*NC];
__device__ __align__(16) float g_psq[NTILE*NC];
__device__ __align__(16) float g_bn[2*NC];
__device__ int g_maxtype;

__device__ __forceinline__ float lrelu(float x) { return x >= 0.f ? x : 0.1f*x; }

// -------- prep: global max of event_types (deterministic) --------
__global__ void k_max(const int* __restrict__ types) {
    __shared__ int sm[1024];
    int t = threadIdx.x, m = 0;
    for (int i = t; i < BS*2048; i += 1024) m = max(m, types[i]);
    sm[t] = m;
    for (int s = 512; s > 0; s >>= 1) {
        __syncthreads();
        if (t < s) sm[t] = max(sm[t], sm[t+s]);
    }
    __syncthreads();
    if (t == 0) g_maxtype = sm[0];
}

// -------- prep: build times + embedded enc --------
__global__ void k_build(const float* __restrict__ et, const int* __restrict__ ty,
                        const float* __restrict__ emb) {
    int idx = blockIdx.x*blockDim.x + threadIdx.x;
    if (idx >= NPOS*NC) return;
    int pos = idx >> 5, c = idx & 31;
    int b = pos / LQ, l = pos - b*LQ;
    float tv = (l == 0) ? 0.f : et[b*2048 + l - 1];
    if (c == 0) g_times[pos] = tv;
    int tp = (l == 0) ? (g_maxtype + 1) : ty[b*2048 + l - 1];
    g_enc[idx] = (tp == 0) ? 0.f : emb[tp*NC + c];
}

// -------- prep: combined weight matrix Wc[layer][584][32] --------
__global__ void k_wc(const float* __restrict__ k3W, const float* __restrict__ k3b,
                     const float* __restrict__ skipW, const float* __restrict__ skipb) {
    int idx = blockIdx.x*blockDim.x + threadIdx.x;
    if (idx >= NL*TILE_ELEMS) return;
    int layer = idx / TILE_ELEMS;
    int rem = idx - layer*TILE_ELEMS;
    int r = rem >> 5, d = rem & 31;
    float v;
    if (r < 512)      v = k3W[layer*16384 + r*32 + d];           // (h*32+c) rows contiguous
    else if (r < 544) v = k3b[layer*1024 + (r-512)*32 + d];
    else if (r < 576) v = skipW[layer*1024 + (r-544)*32 + d];
    else if (r == 576) v = skipb[layer*32 + d];
    else v = 0.f;
    g_Wc[idx] = v;
}

// -------- phase A: build A[tile][k][32] (Gsum + fsum + enc + one) --------
__global__ __launch_bounds__(256) void k_phaseA(int layer, int dil,
        const float* __restrict__ k1W, const float* __restrict__ k1b,
        const float* __restrict__ k2W, const float* __restrict__ k2b) {
    __shared__ float sk1[NH], sk1b[NH], sk2[NH*NH], sk2b[NH];
    __shared__ float As[128*33];
    int tid = threadIdx.x;
    if (tid < NH) { sk1[tid] = k1W[layer*NH + tid]; sk1b[tid] = k1b[layer*NH + tid];
                    sk2b[tid] = k2b[layer*NH + tid]; }
    sk2[tid] = k2W[layer*NH*NH + tid];   // 256 threads == 256 elems
    __syncthreads();

    int lane = tid & 31, warp = tid >> 5;
    int tile = blockIdx.x;

    float G[4][16];
    float FS[4], EN[4], ONE[4];

    #pragma unroll
    for (int wp = 0; wp < 4; wp++) {
        int p = warp*4 + wp;
        int pos = tile*32 + p;
        float fs = 0.f, encl = 0.f, one = 0.f;
        #pragma unroll
        for (int h = 0; h < 16; h++) G[wp][h] = 0.f;
        if (pos < NPOS) {
            one = 1.f;
            int b = pos / LQ, l = pos - b*LQ;
            const float* tb = g_times + b*LQ;
            float tl = tb[l];
            encl = g_enc[pos*NC + lane];
            if (tl != 0.f) {
                for (int k = 0; k < KS; k++) {
                    int j = l - k*dil;
                    if (j < 0) break;
                    float tj = tb[j];
                    if (tj != 0.f) {
                        float dt = tl - tj;
                        int hh = lane & 15;
                        float h1 = lrelu(fmaf(dt, sk1[hh], sk1b[hh]));
                        float h2 = sk2b[hh];
                        #pragma unroll
                        for (int x = 0; x < 16; x++)
                            h2 = fmaf(__shfl_sync(0xffffffffu, h1, x), sk2[x*16 + hh], h2);
                        h2 = lrelu(h2);
                        float g = g_enc[(b*LQ + j)*NC + lane];
                        fs += g;
                        #pragma unroll
                        for (int h = 0; h < 16; h++)
                            G[wp][h] = fmaf(__shfl_sync(0xffffffffu, h2, h), g, G[wp][h]);
                    }
                }
            }
        }
        FS[wp] = fs; EN[wp] = encl; ONE[wp] = one;
    }

    // staged transpose -> coalesced global write
    float* gA = g_A + (long)tile*TILE_ELEMS;
    #pragma unroll
    for (int chunk = 0; chunk < 5; chunk++) {
        __syncthreads();
        if (chunk < 4) {
            #pragma unroll
            for (int wp = 0; wp < 4; wp++) {
                int p = warp*4 + wp;
                #pragma unroll
                for (int hh = 0; hh < 4; hh++)
                    As[(hh*32 + lane)*33 + p] = G[wp][chunk*4 + hh];
            }
        } else {
            #pragma unroll
            for (int wp = 0; wp < 4; wp++) {
                int p = warp*4 + wp;
                As[(lane)*33 + p]      = FS[wp];   // rows 512..543
                As[(32 + lane)*33 + p] = EN[wp];   // rows 544..575
                if (lane == 0) As[64*33 + p] = ONE[wp];   // row 576
                if (lane < 7)  As[(65 + lane)*33 + p] = 0.f; // rows 577..583
            }
        }
        __syncthreads();
        int base = chunk*128;
        int nrows = (chunk < 4) ? 128 : 72;
        for (int idx = tid; idx < nrows*32; idx += 256) {
            int r = idx >> 5, p2 = idx & 31;
            gA[(base + r)*32 + p2] = As[r*33 + p2];
        }
    }
}

// -------- GEMM: raw[pos][d] = A[pos][:] @ Wc[layer][:][d]  + BN partials --------
__global__ __launch_bounds__(128) void k_gemm(int layer) {
    int tile = blockIdx.x;
    int t = threadIdx.x;
    int tx = t & 7;        // n0 = 4*tx
    int ty = t >> 3;       // m0 = 2*ty
    const float* __restrict__ ap = g_A + (long)tile*TILE_ELEMS + 2*ty;
    const float* __restrict__ wp = g_Wc + (long)layer*TILE_ELEMS + 4*tx;
    float a00=0,a01=0,a02=0,a03=0,a10=0,a11=0,a12=0,a13=0;
    #pragma unroll 8
    for (int k = 0; k < KA; k++) {
        float2 a = *reinterpret_cast<const float2*>(ap + k*32);
        float4 w = *reinterpret_cast<const float4*>(wp + k*32);
        a00 = fmaf(a.x, w.x, a00); a01 = fmaf(a.x, w.y, a01);
        a02 = fmaf(a.x, w.z, a02); a03 = fmaf(a.x, w.w, a03);
        a10 = fmaf(a.y, w.x, a10); a11 = fmaf(a.y, w.y, a11);
        a12 = fmaf(a.y, w.z, a12); a13 = fmaf(a.y, w.w, a13);
    }
    float4 r0 = make_float4(a00, a01, a02, a03);
    float4 r1 = make_float4(a10, a11, a12, a13);
    *reinterpret_cast<float4*>(g_raw + (long)(tile*32 + 2*ty + 0)*NC + 4*tx) = r0;
    *reinterpret_cast<float4*>(g_raw + (long)(tile*32 + 2*ty + 1)*NC + 4*tx) = r1;

    __shared__ float ps[16][32], ps2[16][32];
    ps [ty][4*tx+0] = a00 + a10;  ps2[ty][4*tx+0] = a00*a00 + a10*a10;
    ps [ty][4*tx+1] = a01 + a11;  ps2[ty][4*tx+1] = a01*a01 + a11*a11;
    ps [ty][4*tx+2] = a02 + a12;  ps2[ty][4*tx+2] = a02*a02 + a12*a12;
    ps [ty][4*tx+3] = a03 + a13;  ps2[ty][4*tx+3] = a03*a03 + a13*a13;
    __syncthreads();
    if (t < 32) {
        float s = 0.f, s2 = 0.f;
        #pragma unroll
        for (int r = 0; r < 16; r++) { s += ps[r][t]; s2 += ps2[r][t]; }
        g_psum[tile*32 + t] = s;
        g_psq [tile*32 + t] = s2;
    }
}

// -------- BN stats (deterministic fixed-order reduction) --------
__global__ void k_stats(int layer, const float* __restrict__ gamma,
                        const float* __restrict__ beta) {
    __shared__ float ss[8][32], ss2[8][32];
    int t = threadIdx.x;      // 256
    int r = t >> 5, n = t & 31;
    float s = 0.f, s2 = 0.f;
    for (int b = r; b < NTILE; b += 8) { s += g_psum[b*32 + n]; s2 += g_psq[b*32 + n]; }
    ss[r][n] = s; ss2[r][n] = s2;
    __syncthreads();
    if (t < 32) {
        float fs = 0.f, fs2 = 0.f;
        #pragma unroll
        for (int i = 0; i < 8; i++) { fs += ss[i][t]; fs2 += ss2[i][t]; }
        float inv = 1.0f / (float)NPOS;
        float mu = fs * inv;
        float var = fs2 * inv - mu*mu;
        float scale = rsqrtf(var + 1e-5f) * gamma[layer*32 + t];
        g_bn[t]      = scale;
        g_bn[32 + t] = beta[layer*32 + t] - mu*scale;
    }
}

// -------- apply BN + leaky ReLU --------
__global__ void k_apply(float* dst) {
    int idx = blockIdx.x*blockDim.x + threadIdx.x;
    if (idx >= NPOS*NC) return;
    int n = idx & 31;
    float v = fmaf(g_raw[idx], g_bn[n], g_bn[32 + n]);
    v = v >= 0.f ? v : 0.1f*v;
    if (dst) dst[idx] = v;
    else     g_enc[idx] = v;
}

extern "C" void kernel_launch(void* const* d_in, const int* in_sizes, int n_in,
                              void* d_out, int out_size) {
    const float* event_times = (const float*)d_in[0];
    const int*   event_types = (const int*)  d_in[1];
    // d_in[2] = emb
    const float* emb   = (const float*)d_in[2];
    const float* k1W   = (const float*)d_in[3];
    const float* k1b   = (const float*)d_in[4];
    const float* k2W   = (const float*)d_in[5];
    const float* k2b   = (const float*)d_in[6];
    const float* k3W   = (const float*)d_in[7];
    const float* k3b   = (const float*)d_in[8];
    const float* skipW = (const float*)d_in[9];
    const float* skipb = (const float*)d_in[10];
    const float* gamma = (const float*)d_in[11];
    const float* beta  = (const float*)d_in[12];
    float* out = (float*)d_out;

    k_max<<<1, 1024>>>(event_types);
    k_build<<<(NPOS*NC + 255)/256, 256>>>(event_times, event_types, emb);
    k_wc<<<(NL*TILE_ELEMS + 255)/256, 256>>>(k3W, k3b, skipW, skipb);

    const int dil[NL] = {1, 2, 4, 8};
    for (int i = 0; i < NL; i++) {
        k_phaseA<<<NTILE, 256>>>(i, dil[i], k1W, k1b, k2W, k2b);
        k_gemm<<<NTILE, 128>>>(i);
        k_stats<<<1, 256>>>(i, gamma, beta);
        k_apply<<<(NPOS*NC + 255)/256, 256>>>((i == NL-1) ? out : nullptr);
    }
}

// round 2
// speedup vs baseline: 1.2850x; 1.2850x over previous
#include <cuda_runtime.h>

#define BS 8
#define LQ 2049
#define NC 32
#define NH 16
#define KS 5
#define NL 4
#define NPOS (BS*LQ)            // 16392
#define NTILE 513               // ceil(NPOS/32)
#define KA 584                  // 512 Gsum + 32 fsum + 32 enc + 1 one + 7 pad
#define TILE_ELEMS (KA*NC)      // 18688
#define ASTRIDE 596             // padded A row stride (conflict-free LDS.128)
#define SMEM_FLOATS (64 + 32*ASTRIDE + 2048)   // bn + A + ps + ps2
#define SMEM_BYTES (SMEM_FLOATS*4)             // 84736 B

// -------- device scratch --------
__device__ __align__(16) float g_times[BS*LQ];
__device__ __align__(16) float g_enc[NPOS*NC];
__device__ __align__(16) float g_raw[2][NTILE*32*NC];   // ping-pong
__device__ __align__(16) float g_H2[NPOS*KS*NH];        // 5.2 MB
__device__ __align__(16) float g_Wc[NL*TILE_ELEMS];
__device__ __align__(16) float g_psum[NTILE*NC];
__device__ __align__(16) float g_psq[NTILE*NC];
__device__ __align__(16) float g_bn[2*NC];
__device__ int g_maxtype;

__device__ __forceinline__ float lrelu(float x) { return x >= 0.f ? x : 0.1f*x; }

// -------- prep: global max of event_types --------
__global__ void k_max(const int* __restrict__ types) {
    __shared__ int sm[1024];
    int t = threadIdx.x, m = 0;
    for (int i = t; i < BS*2048; i += 1024) m = max(m, types[i]);
    sm[t] = m;
    for (int s = 512; s > 0; s >>= 1) {
        __syncthreads();
        if (t < s) sm[t] = max(sm[t], sm[t+s]);
    }
    __syncthreads();
    if (t == 0) g_maxtype = sm[0];
}

// -------- prep: build times + embedded enc --------
__global__ void k_build(const float* __restrict__ et, const int* __restrict__ ty,
                        const float* __restrict__ emb) {
    int idx = blockIdx.x*blockDim.x + threadIdx.x;
    if (idx >= NPOS*NC) return;
    int pos = idx >> 5, c = idx & 31;
    int b = pos / LQ, l = pos - b*LQ;
    float tv = (l == 0) ? 0.f : et[b*2048 + l - 1];
    if (c == 0) g_times[pos] = tv;
    int tp = (l == 0) ? (g_maxtype + 1) : ty[b*2048 + l - 1];
    g_enc[idx] = (tp == 0) ? 0.f : emb[tp*NC + c];
}

// -------- prep: combined weight matrix Wc[layer][584][32] --------
__global__ void k_wc(const float* __restrict__ k3W, const float* __restrict__ k3b,
                     const float* __restrict__ skipW, const float* __restrict__ skipb) {
    int idx = blockIdx.x*blockDim.x + threadIdx.x;
    if (idx >= NL*TILE_ELEMS) return;
    int layer = idx / TILE_ELEMS;
    int rem = idx - layer*TILE_ELEMS;
    int r = rem >> 5, d = rem & 31;
    float v;
    if (r < 512)      v = k3W[layer*16384 + r*32 + d];
    else if (r < 544) v = k3b[layer*1024 + (r-512)*32 + d];
    else if (r < 576) v = skipW[layer*1024 + (r-544)*32 + d];
    else if (r == 576) v = skipb[layer*32 + d];
    else v = 0.f;
    g_Wc[idx] = v;
}

// -------- per-layer: kernel MLP precompute  H2[pos][k][16] (masked) --------
__global__ __launch_bounds__(256) void k_mlp(int layer, int dil,
        const float* __restrict__ k1W, const float* __restrict__ k1b,
        const float* __restrict__ k2W, const float* __restrict__ k2b) {
    __shared__ float sk1[NH], sk1b[NH], sk2[NH*NH], sk2b[NH];
    int t = threadIdx.x;
    if (t < NH) { sk1[t] = k1W[layer*NH + t]; sk1b[t] = k1b[layer*NH + t];
                  sk2b[t] = k2b[layer*NH + t]; }
    sk2[t] = k2W[layer*NH*NH + t];
    __syncthreads();
    int idx = blockIdx.x*256 + t;
    if (idx >= NPOS*KS) return;
    int pos = idx / KS, k = idx - pos*KS;
    int b = pos / LQ, l = pos - b*LQ;
    float out[NH];
    bool valid = false;
    int j = l - k*dil;
    float tl = g_times[pos];
    if (j >= 0 && tl != 0.f) {
        float tj = g_times[b*LQ + j];
        if (tj != 0.f) {
            valid = true;
            float dt = tl - tj;
            float h1[NH];
            #pragma unroll
            for (int h = 0; h < NH; h++) h1[h] = lrelu(fmaf(dt, sk1[h], sk1b[h]));
            #pragma unroll
            for (int hh = 0; hh < NH; hh++) {
                float s = sk2b[hh];
                #pragma unroll
                for (int x = 0; x < NH; x++) s = fmaf(h1[x], sk2[x*NH + hh], s);
                out[hh] = lrelu(s);
            }
        }
    }
    if (!valid) {
        #pragma unroll
        for (int h = 0; h < NH; h++) out[h] = 0.f;
    }
    float* dst = g_H2 + (pos*KS + k)*NH;
    #pragma unroll
    for (int q = 0; q < 4; q++)
        *reinterpret_cast<float4*>(dst + 4*q) =
            make_float4(out[4*q], out[4*q+1], out[4*q+2], out[4*q+3]);
}

// -------- fused: gather/Gsum build (smem A) + GEMM + BN partials --------
__global__ __launch_bounds__(256) void k_fused(int layer, int dil, int first) {
    extern __shared__ float sm[];
    float* s_bn = sm;                 // 64
    float* s_A  = sm + 64;            // 32*ASTRIDE
    float* s_ps = s_A + 32*ASTRIDE;   // 1024
    float* s_ps2 = s_ps + 1024;       // 1024
    int t = threadIdx.x;
    int lane = t & 31, warp = t >> 5;
    int tile = blockIdx.x;
    const float* raw_in = g_raw[(layer + 1) & 1];
    float* raw_out = g_raw[layer & 1];

    if (!first && t < 64) s_bn[t] = g_bn[t];
    __syncthreads();

    // ---- phase A: 8 warps x 4 positions; lane = channel c ----
    #pragma unroll
    for (int wp = 0; wp < 4; wp++) {
        int p = warp*4 + wp;
        int pos = tile*32 + p;
        float G[NH];
        #pragma unroll
        for (int h = 0; h < NH; h++) G[h] = 0.f;
        float fs = 0.f, en = 0.f, one = 0.f;
        if (pos < NPOS) {
            one = 1.f;
            int b = pos / LQ, l = pos - b*LQ;
            float tl = g_times[pos];
            if (first) en = g_enc[pos*NC + lane];
            else {
                float v = fmaf(raw_in[pos*NC + lane], s_bn[lane], s_bn[32 + lane]);
                en = v >= 0.f ? v : 0.1f*v;
            }
            if (tl != 0.f) {
                const float* h2p = g_H2 + pos*(KS*NH);
                for (int k = 0; k < KS; k++) {
                    int j = l - k*dil;
                    if (j < 0) break;
                    float tj = g_times[b*LQ + j];
                    if (tj != 0.f) {
                        int pj = pos - k*dil;
                        float g;
                        if (first) g = g_enc[pj*NC + lane];
                        else {
                            float v = fmaf(raw_in[pj*NC + lane], s_bn[lane], s_bn[32 + lane]);
                            g = v >= 0.f ? v : 0.1f*v;
                        }
                        fs += g;
                        float4 h0 = *reinterpret_cast<const float4*>(h2p + k*NH + 0);
                        float4 h1 = *reinterpret_cast<const float4*>(h2p + k*NH + 4);
                        float4 h2 = *reinterpret_cast<const float4*>(h2p + k*NH + 8);
                        float4 h3 = *reinterpret_cast<const float4*>(h2p + k*NH + 12);
                        G[0] = fmaf(h0.x, g, G[0]);  G[1] = fmaf(h0.y, g, G[1]);
                        G[2] = fmaf(h0.z, g, G[2]);  G[3] = fmaf(h0.w, g, G[3]);
                        G[4] = fmaf(h1.x, g, G[4]);  G[5] = fmaf(h1.y, g, G[5]);
                        G[6] = fmaf(h1.z, g, G[6]);  G[7] = fmaf(h1.w, g, G[7]);
                        G[8] = fmaf(h2.x, g, G[8]);  G[9] = fmaf(h2.y, g, G[9]);
                        G[10] = fmaf(h2.z, g, G[10]); G[11] = fmaf(h2.w, g, G[11]);
                        G[12] = fmaf(h3.x, g, G[12]); G[13] = fmaf(h3.y, g, G[13]);
                        G[14] = fmaf(h3.z, g, G[14]); G[15] = fmaf(h3.w, g, G[15]);
                    }
                }
            }
        }
        float* row = s_A + p*ASTRIDE;
        #pragma unroll
        for (int h = 0; h < NH; h++) row[h*32 + lane] = G[h];
        row[512 + lane] = fs;
        row[544 + lane] = en;
        if (lane == 0) row[576] = one;
        if (lane < 7)  row[577 + lane] = 0.f;
    }
    __syncthreads();

    // ---- GEMM: 256 threads, each 1 pos x 4 d; K=584 in float4 chunks ----
    int tx = t & 7;        // d0 = 4*tx
    int ty = t >> 3;       // pos within tile
    const float* Ap = s_A + ty*ASTRIDE;
    const float* Wl = g_Wc + layer*TILE_ELEMS + 4*tx;
    float ax = 0.f, ay = 0.f, az = 0.f, aw = 0.f;
    #pragma unroll 2
    for (int kk = 0; kk < KA/4; kk++) {
        float4 a  = *reinterpret_cast<const float4*>(Ap + kk*4);
        float4 w0 = *reinterpret_cast<const float4*>(Wl + (4*kk+0)*32);
        float4 w1 = *reinterpret_cast<const float4*>(Wl + (4*kk+1)*32);
        float4 w2 = *reinterpret_cast<const float4*>(Wl + (4*kk+2)*32);
        float4 w3 = *reinterpret_cast<const float4*>(Wl + (4*kk+3)*32);
        ax = fmaf(a.x, w0.x, ax); ay = fmaf(a.x, w0.y, ay);
        az = fmaf(a.x, w0.z, az); aw = fmaf(a.x, w0.w, aw);
        ax = fmaf(a.y, w1.x, ax); ay = fmaf(a.y, w1.y, ay);
        az = fmaf(a.y, w1.z, az); aw = fmaf(a.y, w1.w, aw);
        ax = fmaf(a.z, w2.x, ax); ay = fmaf(a.z, w2.y, ay);
        az = fmaf(a.z, w2.z, az); aw = fmaf(a.z, w2.w, aw);
        ax = fmaf(a.w, w3.x, ax); ay = fmaf(a.w, w3.y, ay);
        az = fmaf(a.w, w3.z, az); aw = fmaf(a.w, w3.w, aw);
    }
    *reinterpret_cast<float4*>(raw_out + (tile*32 + ty)*NC + 4*tx) =
        make_float4(ax, ay, az, aw);

    // ---- BN partials (deterministic) ----
    s_ps [ty*32 + 4*tx+0] = ax;  s_ps2[ty*32 + 4*tx+0] = ax*ax;
    s_ps [ty*32 + 4*tx+1] = ay;  s_ps2[ty*32 + 4*tx+1] = ay*ay;
    s_ps [ty*32 + 4*tx+2] = az;  s_ps2[ty*32 + 4*tx+2] = az*az;
    s_ps [ty*32 + 4*tx+3] = aw;  s_ps2[ty*32 + 4*tx+3] = aw*aw;
    __syncthreads();
    if (t < 32) {
        float s = 0.f, s2 = 0.f;
        #pragma unroll
        for (int r = 0; r < 32; r++) { s += s_ps[r*32 + t]; s2 += s_ps2[r*32 + t]; }
        g_psum[tile*32 + t] = s;
        g_psq [tile*32 + t] = s2;
    }
}

// -------- BN stats (deterministic fixed-order reduction) --------
__global__ void k_stats(int layer, const float* __restrict__ gamma,
                        const float* __restrict__ beta) {
    __shared__ float ss[8][32], ss2[8][32];
    int t = threadIdx.x;      // 256
    int r = t >> 5, n = t & 31;
    float s = 0.f, s2 = 0.f;
    for (int b = r; b < NTILE; b += 8) { s += g_psum[b*32 + n]; s2 += g_psq[b*32 + n]; }
    ss[r][n] = s; ss2[r][n] = s2;
    __syncthreads();
    if (t < 32) {
        float fs = 0.f, fs2 = 0.f;
        #pragma unroll
        for (int i = 0; i < 8; i++) { fs += ss[i][t]; fs2 += ss2[i][t]; }
        float inv = 1.0f / (float)NPOS;
        float mu = fs * inv;
        float var = fs2 * inv - mu*mu;
        float scale = rsqrtf(var + 1e-5f) * gamma[layer*32 + t];
        g_bn[t]      = scale;
        g_bn[32 + t] = beta[layer*32 + t] - mu*scale;
    }
}

// -------- final apply: BN + leaky ReLU -> output --------
__global__ void k_apply(float* dst, int buf) {
    int idx = blockIdx.x*blockDim.x + threadIdx.x;
    if (idx >= NPOS*NC) return;
    int n = idx & 31;
    float v = fmaf(g_raw[buf][idx], g_bn[n], g_bn[32 + n]);
    dst[idx] = v >= 0.f ? v : 0.1f*v;
}

extern "C" void kernel_launch(void* const* d_in, const int* in_sizes, int n_in,
                              void* d_out, int out_size) {
    const float* event_times = (const float*)d_in[0];
    const int*   event_types = (const int*)  d_in[1];
    const float* emb   = (const float*)d_in[2];
    const float* k1W   = (const float*)d_in[3];
    const float* k1b   = (const float*)d_in[4];
    const float* k2W   = (const float*)d_in[5];
    const float* k2b   = (const float*)d_in[6];
    const float* k3W   = (const float*)d_in[7];
    const float* k3b   = (const float*)d_in[8];
    const float* skipW = (const float*)d_in[9];
    const float* skipb = (const float*)d_in[10];
    const float* gamma = (const float*)d_in[11];
    const float* beta  = (const float*)d_in[12];
    float* out = (float*)d_out;

    static int attr_done = 0;
    if (!attr_done) {
        cudaFuncSetAttribute(k_fused, cudaFuncAttributeMaxDynamicSharedMemorySize,
                             SMEM_BYTES);
        attr_done = 1;
    }

    k_max<<<1, 1024>>>(event_types);
    k_build<<<(NPOS*NC + 255)/256, 256>>>(event_times, event_types, emb);
    k_wc<<<(NL*TILE_ELEMS + 255)/256, 256>>>(k3W, k3b, skipW, skipb);

    const int dil[NL] = {1, 2, 4, 8};
    for (int i = 0; i < NL; i++) {
        k_mlp<<<(NPOS*KS + 255)/256, 256>>>(i, dil[i], k1W, k1b, k2W, k2b);
        k_fused<<<NTILE, 256, SMEM_BYTES>>>(i, dil[i], i == 0);
        k_stats<<<1, 256>>>(i, gamma, beta);
    }
    k_apply<<<(NPOS*NC + 255)/256, 256>>>(out, (NL-1) & 1);
}